// round 1
// baseline (speedup 1.0000x reference)
#include <cuda_runtime.h>
#include <math.h>

// Problem constants (fixed by the dataset)
#define NN 10000   // nodes
#define PP 25000   // edge-pairs
#define BB 8       // batch
#define FF 16      // feats
#define MM 32      // MLP width
#define LL 2       // GNN layers
#define HH 2       // MLP hidden layers
#define TWO_F (2*FF)          // 32
#define NODE_STRIDE (BB*FF)   // 128 floats per node
#define XELEMS (NN*NODE_STRIDE)

// ping-pong node-state buffers, [N][B][F] layout
__device__ float g_x[2][XELEMS];

// ---------------------------------------------------------------------------
// h [B][N][F]  ->  g_x[buf] [N][B][F]
__global__ void transpose_in_kernel(const float* __restrict__ h, int buf) {
    int idx = blockIdx.x * blockDim.x + threadIdx.x;
    if (idx >= XELEMS) return;
    int n = idx / NODE_STRIDE;
    int r = idx - n * NODE_STRIDE;
    int b = r >> 4;            // /FF
    int f = r & 15;            // %FF
    g_x[buf][idx] = h[(size_t)b * NN * FF + (size_t)n * FF + f];
}

// g_x[buf] [N][B][F] -> out [B][N][F]
__global__ void transpose_out_kernel(float* __restrict__ out, int buf) {
    int idx = blockIdx.x * blockDim.x + threadIdx.x;
    if (idx >= XELEMS) return;
    int b = idx / (NN * FF);
    int r = idx - b * NN * FF;
    int n = r >> 4;
    int f = r & 15;
    out[idx] = g_x[buf][n * NODE_STRIDE + b * FF + f];
}

__global__ void zero_kernel(int buf) {
    int idx = blockIdx.x * blockDim.x + threadIdx.x;
    if (idx < XELEMS) g_x[buf][idx] = 0.0f;
}

// ---------------------------------------------------------------------------
// One warp per edge-pair (edge index PP = the fixed edge with shared weights).
// Lane m owns output column m; 8 batch accumulators live in registers;
// activations are broadcast from shared memory; per-k weight loads are a
// fully coalesced 128B line per warp.
#define WPB 8  // warps per block

__global__ void __launch_bounds__(WPB * 32)
edge_kernel(const float* __restrict__ Wi0,  const float* __restrict__ Wih,
            const float* __restrict__ Wiout,const float* __restrict__ bi0,
            const float* __restrict__ bih,  const float* __restrict__ biout,
            const float* __restrict__ Wf0,  const float* __restrict__ Wfh,
            const float* __restrict__ Wfout,const float* __restrict__ bf0,
            const float* __restrict__ bfh,  const float* __restrict__ bfout,
            const int* __restrict__ src,    const int* __restrict__ dst,
            int layer, int curbuf, int nxtbuf)
{
    __shared__ float smA[WPB][BB][MM];
    __shared__ float smB[WPB][BB][MM];

    const int w    = threadIdx.x >> 5;
    const int lane = threadIdx.x & 31;
    const int e    = blockIdx.x * WPB + w;
    if (e > PP) return;

    const bool fx   = (e == PP);
    const int  eidx = fx ? 2 * PP : e;   // fixed edge is the last entry
    const int  d = dst[eidx];
    const int  s = src[eidx];

    const long Pp = fx ? 1 : PP;
    const long pe = fx ? 0 : e;

    const float* W0   = (fx ? Wf0   : Wi0)   + ((long)layer * Pp + pe) * (TWO_F * MM);
    const float* b0   = (fx ? bf0   : bi0)   + ((long)layer * Pp + pe) * MM;
    const float* Wout = (fx ? Wfout : Wiout) + ((long)layer * Pp + pe) * (MM * FF);
    const float* bout = (fx ? bfout : biout) + ((long)layer * Pp + pe) * FF;
    const float* WhB  = fx ? Wfh : Wih;
    const float* bhB  = fx ? bfh : bih;

    const float* xcur = g_x[curbuf];
    float*       xnxt = g_x[nxtbuf];

    // ---- gather edge input: [B][2F] = concat(x[dst], x[src]) on feature axis
    const float* xd = xcur + (long)d * NODE_STRIDE;
    const float* xs = xcur + (long)s * NODE_STRIDE;
    #pragma unroll
    for (int b = 0; b < BB; b++) {
        smA[w][b][lane] = (lane < FF) ? xd[b * FF + lane]
                                      : xs[b * FF + (lane - FF)];
    }
    __syncwarp();

    float acc[BB];

    // ---- layer 0: [B,2F] @ [2F,M] + silu
    {
        const float bias = b0[lane];
        #pragma unroll
        for (int b = 0; b < BB; b++) acc[b] = bias;
        #pragma unroll
        for (int k = 0; k < TWO_F; k++) {
            const float wv = W0[k * MM + lane];
            #pragma unroll
            for (int b = 0; b < BB; b++)
                acc[b] = fmaf(smA[w][b][k], wv, acc[b]);
        }
        #pragma unroll
        for (int b = 0; b < BB; b++) {
            const float v = acc[b];
            smB[w][b][lane] = v / (1.0f + __expf(-v));
        }
    }
    __syncwarp();

    // ---- hidden layers: [B,M] @ [M,M] + silu, ping-pong smB <-> smA
    float (*cur)[MM] = smB[w];
    float (*nxt)[MM] = smA[w];
    #pragma unroll
    for (int i = 0; i < HH; i++) {
        const float* Wh = WhB + (((long)layer * HH + i) * Pp + pe) * (MM * MM);
        const float* bh = bhB + (((long)layer * HH + i) * Pp + pe) * MM;
        const float bias = bh[lane];
        #pragma unroll
        for (int b = 0; b < BB; b++) acc[b] = bias;
        #pragma unroll
        for (int k = 0; k < MM; k++) {
            const float wv = Wh[k * MM + lane];
            #pragma unroll
            for (int b = 0; b < BB; b++)
                acc[b] = fmaf(cur[b][k], wv, acc[b]);
        }
        #pragma unroll
        for (int b = 0; b < BB; b++) {
            const float v = acc[b];
            nxt[b][lane] = v / (1.0f + __expf(-v));
        }
        __syncwarp();
        float (*t)[MM] = cur; cur = nxt; nxt = t;
    }

    // ---- output layer: [B,M] @ [M,F] ; lanes 0-15 -> batches 0-3, 16-31 -> 4-7
    const int f  = lane & 15;
    const int bg = lane >> 4;
    float o[4];
    const float ob = bout[f];
    #pragma unroll
    for (int j = 0; j < 4; j++) o[j] = ob;
    #pragma unroll
    for (int k = 0; k < MM; k++) {
        const float wv = Wout[k * FF + f];
        #pragma unroll
        for (int j = 0; j < 4; j++)
            o[j] = fmaf(cur[bg * 4 + j][k], wv, o[j]);
    }

    // ---- scatter: +msg to dst, -msg to src (fixed edge: + to dst only)
    float* yd = xnxt + (long)d * NODE_STRIDE;
    float* ys = xnxt + (long)s * NODE_STRIDE;
    #pragma unroll
    for (int j = 0; j < 4; j++) {
        const int b = bg * 4 + j;
        atomicAdd(yd + b * FF + f, o[j]);
        if (!fx) atomicAdd(ys + b * FF + f, -o[j]);
    }
}

// ---------------------------------------------------------------------------
extern "C" void kernel_launch(void* const* d_in, const int* in_sizes, int n_in,
                              void* d_out, int out_size) {
    const float* h     = (const float*)d_in[0];
    const float* Wi0   = (const float*)d_in[1];
    const float* Wih   = (const float*)d_in[2];
    const float* Wiout = (const float*)d_in[3];
    const float* bi0   = (const float*)d_in[4];
    const float* bih   = (const float*)d_in[5];
    const float* biout = (const float*)d_in[6];
    const float* Wf0   = (const float*)d_in[7];
    const float* Wfh   = (const float*)d_in[8];
    const float* Wfout = (const float*)d_in[9];
    const float* bf0   = (const float*)d_in[10];
    const float* bfh   = (const float*)d_in[11];
    const float* bfout = (const float*)d_in[12];
    const int*   src   = (const int*)d_in[13];
    const int*   dst   = (const int*)d_in[14];
    float*       out   = (float*)d_out;

    const int tb = 256;
    const int xblocks = (XELEMS + tb - 1) / tb;
    const int eblocks = (PP + 1 + WPB - 1) / WPB;

    transpose_in_kernel<<<xblocks, tb>>>(h, 0);

    // layer 0: read buf0 -> write buf1
    zero_kernel<<<xblocks, tb>>>(1);
    edge_kernel<<<eblocks, WPB * 32>>>(Wi0, Wih, Wiout, bi0, bih, biout,
                                       Wf0, Wfh, Wfout, bf0, bfh, bfout,
                                       src, dst, /*layer=*/0, /*cur=*/0, /*nxt=*/1);

    // layer 1: read buf1 -> write buf0
    zero_kernel<<<xblocks, tb>>>(0);
    edge_kernel<<<eblocks, WPB * 32>>>(Wi0, Wih, Wiout, bi0, bih, biout,
                                       Wf0, Wfh, Wfout, bf0, bfh, bfout,
                                       src, dst, /*layer=*/1, /*cur=*/1, /*nxt=*/0);

    transpose_out_kernel<<<xblocks, tb>>>(out, 0);
}